// round 16
// baseline (speedup 1.0000x reference)
#include <cuda_runtime.h>
#include <cuda_pipeline.h>

#define BB 4
#define CC 64
#define HH 128
#define WW 416
#define HW (HH*WW)
#define CHW (CC*HH*WW)

// Scratch for warped x2 (no cudaMalloc allowed)
__device__ float g_x2w[(size_t)BB*CHW];

__device__ __forceinline__ float lrelu(float v) { return v >= 0.f ? v : 0.1f*v; }

// Side stream + fork/join events, created once at process init (no device
// memory allocation; just stream/event handles).
struct StreamInit {
    cudaStream_t s;
    cudaEvent_t e_fork, e_join;
    StreamInit() {
        cudaStreamCreateWithFlags(&s, cudaStreamNonBlocking);
        cudaEventCreateWithFlags(&e_fork, cudaEventDisableTiming);
        cudaEventCreateWithFlags(&e_join, cudaEventDisableTiming);
    }
};
static StreamInit g_si;

// ===========================================================================
// Kernel 1: bilinear warp of x2 -> g_x2w. One pixel per thread, weights and
// indices register-resident, 64-c gather loop with deep unroll for MLP.
// ===========================================================================
__global__ __launch_bounds__(416)
void warp_kernel(const float* __restrict__ x2, const float* __restrict__ flow) {
    const int x = threadIdx.x;            // 0..415
    const int y = blockIdx.y, b = blockIdx.z;

    const float fx = flow[((size_t)(b*2+0)*HH + y)*WW + x];
    const float fy = flow[((size_t)(b*2+1)*HH + y)*WW + x];
    const float gx = (float)x + fx;
    const float gy = (float)y + fy;
    const float x0f = floorf(gx), y0f = floorf(gy);
    const float wx = gx - x0f, wy = gy - y0f;
    const int x0 = (int)x0f, y0 = (int)y0f;
    const int x1i = x0 + 1,  y1i = y0 + 1;

    const float vx0 = (x0  >= 0 && x0  < WW) ? 1.f : 0.f;
    const float vx1 = (x1i >= 0 && x1i < WW) ? 1.f : 0.f;
    const float vy0 = (y0  >= 0 && y0  < HH) ? 1.f : 0.f;
    const float vy1 = (y1i >= 0 && y1i < HH) ? 1.f : 0.f;

    const int x0c = min(max(x0, 0), WW-1);
    const int x1c = min(max(x1i,0), WW-1);
    const int y0c = min(max(y0, 0), HH-1);
    const int y1c = min(max(y1i,0), HH-1);

    const float w00 = (1.f-wx)*(1.f-wy)*vx0*vy0;
    const float w01 = wx*(1.f-wy)*vx1*vy0;
    const float w10 = (1.f-wx)*wy*vx0*vy1;
    const float w11 = wx*wy*vx1*vy1;
    const int i00 = y0c*WW + x0c;
    const int i01 = y0c*WW + x1c;
    const int i10 = y1c*WW + x0c;
    const int i11 = y1c*WW + x1c;

    const float* xb = x2 + (size_t)b*CHW;
    float* ob = g_x2w + (size_t)b*CHW + (size_t)y*WW + x;
#pragma unroll 8
    for (int c = 0; c < CC; c++) {
        const float* p = xb + (size_t)c*HW;
        ob[(size_t)c*HW] = w00*__ldg(p+i00) + w01*__ldg(p+i01)
                         + w10*__ldg(p+i10) + w11*__ldg(p+i11);
    }
}

// ===========================================================================
// Kernel 2: 192-ch disparity cost volume (champion disp path, unchanged)
// ===========================================================================
#define TXD 104
#define RWD 296
#define CTD 16
#define NTD (CC/CTD)
#define DISP_BUF (CTD*TXD + CTD*RWD)    // 6400 floats per buffer
#define DSP_SMEM (2*DISP_BUF*4)         // 51200 B

__global__ __launch_bounds__(320, 2)
void disp_kernel(const float* __restrict__ x1, const float* __restrict__ r1,
                 float* __restrict__ out) {
    extern __shared__ float sm[];
    const int y = blockIdx.y, b = blockIdx.z;
    const int t = threadIdx.x;
    const int x0t = blockIdx.x * TXD;
    const int dg = t / 26;
    const int xg = t - dg*26;
    const bool act = (t < 312);

    const float* x1p = x1 + (size_t)b*CHW + (size_t)y*WW + x0t;
    const float* rp  = r1 + (size_t)b*CHW + (size_t)y*WW;

    float acc[16][4];
#pragma unroll
    for (int i = 0; i < 16; i++)
#pragma unroll
        for (int j = 0; j < 4; j++) acc[i][j] = 0.f;

    auto load_tile = [&](int bi, int kt) {
        float* da = sm + bi*DISP_BUF;
        float* dr = da + CTD*TXD;
        const int ct = kt * CTD;
#pragma unroll
        for (int i = t; i < CTD*26; i += 320) {
            int c = i / 26, x4 = (i - 26*c) * 4;
            __pipeline_memcpy_async(da + c*TXD + x4,
                                    x1p + (size_t)(ct+c)*HW + x4, 16);
        }
#pragma unroll
        for (int i = t; i < CTD*74; i += 320) {
            int c = i / 74, x4 = (i - 74*c) * 4;
            int gx = x0t - 96 + x4;
            float* dst = dr + c*RWD + x4;
            if ((unsigned)gx < WW)
                __pipeline_memcpy_async(dst, rp + (size_t)(ct+c)*HW + gx, 16);
            else
                *reinterpret_cast<float4*>(dst) = make_float4(0.f,0.f,0.f,0.f);
        }
    };

    load_tile(0, 0);
    __pipeline_commit();

    for (int k = 0; k < NTD; k++) {
        if (k + 1 < NTD) {
            load_tile((k+1) & 1, k+1);
            __pipeline_commit();
            __pipeline_wait_prior(1);
        } else {
            __pipeline_wait_prior(0);
        }
        __syncthreads();

        if (act) {
            const float* da = sm + (k&1)*DISP_BUF;
            const float* ap = da + xg*4;
            const float* bp = da + CTD*TXD + xg*4 + dg*16;
#pragma unroll 4
            for (int c = 0; c < CTD; c++) {
                const float4 a  = *reinterpret_cast<const float4*>(ap + c*TXD);
                const float4 q0 = *reinterpret_cast<const float4*>(bp + c*RWD);
                const float4 q1 = *reinterpret_cast<const float4*>(bp + c*RWD + 4);
                const float4 q2 = *reinterpret_cast<const float4*>(bp + c*RWD + 8);
                const float4 q3 = *reinterpret_cast<const float4*>(bp + c*RWD + 12);
                const float4 q4 = *reinterpret_cast<const float4*>(bp + c*RWD + 16);
                const float bv[20] = {q0.x,q0.y,q0.z,q0.w, q1.x,q1.y,q1.z,q1.w,
                                      q2.x,q2.y,q2.z,q2.w, q3.x,q3.y,q3.z,q3.w,
                                      q4.x,q4.y,q4.z,q4.w};
#pragma unroll
                for (int dj = 0; dj < 16; dj++) {
                    acc[dj][0] += a.x*bv[dj+0];
                    acc[dj][1] += a.y*bv[dj+1];
                    acc[dj][2] += a.z*bv[dj+2];
                    acc[dj][3] += a.w*bv[dj+3];
                }
            }
        }
        __syncthreads();
    }

    if (act) {
        float* op = out + ((size_t)(b*273 + 81 + dg*16)*HH + y)*WW + x0t + xg*4;
#pragma unroll
        for (int dj = 0; dj < 16; dj++) {
            float4 v;
            v.x = lrelu(acc[dj][0]);
            v.y = lrelu(acc[dj][1]);
            v.z = lrelu(acc[dj][2]);
            v.w = lrelu(acc[dj][3]);
            *reinterpret_cast<float4*>(op + (size_t)dj*HW) = v;
        }
    }
}

// ===========================================================================
// Kernel 3: 81-ch cost volume, 2 output rows per block (R14 champion)
// ===========================================================================
#define TXC 104
#define CTC 8
#define BWC 112
#define NTC (CC/CTC)
#define C2_AROWS 16                         // 2 ysub x 8 c
#define C2_BUF (C2_AROWS*TXC + 10*CTC*BWC)  // 10624 floats
#define C2_SMEM (2*C2_BUF*4)                // 84992 B

__global__ __launch_bounds__(256, 2)
void corr_kernel(const float* __restrict__ x1, float* __restrict__ out) {
    extern __shared__ float sm[];

    const int x0t = blockIdx.x * TXC;
    const int y0 = blockIdx.y * 2;
    const int b = blockIdx.z;
    const int t = threadIdx.x;
    const int dy = t / 26;
    const int xg = t - dy*26;
    const bool act = (t < 234);

    const float* x1b = x1 + (size_t)b*CHW + x0t;
    const float* wp  = g_x2w + (size_t)b*CHW;

    const int ca = t / 26, xa = (t - 26*ca) * 4;
    const int cb = t / 28, xb4 = (t - 28*cb) * 4;
    const int gx2 = x0t - 4 + xb4;
    const bool px = ((unsigned)gx2 < WW);

    float acc0[9][4], acc1[9][4];
#pragma unroll
    for (int i = 0; i < 9; i++)
#pragma unroll
        for (int j = 0; j < 4; j++) { acc0[i][j] = 0.f; acc1[i][j] = 0.f; }

    auto load_tile = [&](int bi, int kt) {
        float* da = sm + bi*C2_BUF;
        float* db = da + C2_AROWS*TXC;
        const int ct = kt * CTC;
        if (t < 208) {
            const float* s0 = x1b + (size_t)(ct+ca)*HW + (size_t)y0*WW + xa;
            __pipeline_memcpy_async(da + ca*TXC + xa, s0, 16);
            __pipeline_memcpy_async(da + (8+ca)*TXC + xa, s0 + WW, 16);
        }
        if (t < 224) {
            const float* srcb = wp + (size_t)(ct+cb)*HW + gx2;
            float* dstb = db + cb*BWC + xb4;
#pragma unroll
            for (int r = 0; r < 10; r++) {
                const int gy2 = y0 + r - 4;
                if (px && (unsigned)gy2 < HH)
                    __pipeline_memcpy_async(dstb + r*(CTC*BWC), srcb + gy2*WW, 16);
                else
                    *reinterpret_cast<float4*>(dstb + r*(CTC*BWC)) =
                        make_float4(0.f,0.f,0.f,0.f);
            }
        }
    };

    load_tile(0, 0);
    __pipeline_commit();

    for (int k = 0; k < NTC; k++) {
        if (k + 1 < NTC) {
            load_tile((k+1) & 1, k+1);
            __pipeline_commit();
            __pipeline_wait_prior(1);
        } else {
            __pipeline_wait_prior(0);
        }
        __syncthreads();

        if (act) {
            const float* da = sm + (k&1)*C2_BUF;
            const float* ap0 = da + xg*4;
            const float* ap1 = da + 8*TXC + xg*4;
            const float* bp0 = da + C2_AROWS*TXC + dy*(CTC*BWC) + xg*4;
            const float* bp1 = bp0 + (CTC*BWC);
#pragma unroll
            for (int c = 0; c < CTC; c++) {
                const float4 a0 = *reinterpret_cast<const float4*>(ap0 + c*TXC);
                const float4 a1 = *reinterpret_cast<const float4*>(ap1 + c*TXC);
                const float4 p0 = *reinterpret_cast<const float4*>(bp0 + c*BWC);
                const float4 p1 = *reinterpret_cast<const float4*>(bp0 + c*BWC + 4);
                const float4 p2 = *reinterpret_cast<const float4*>(bp0 + c*BWC + 8);
                const float4 q0 = *reinterpret_cast<const float4*>(bp1 + c*BWC);
                const float4 q1 = *reinterpret_cast<const float4*>(bp1 + c*BWC + 4);
                const float4 q2 = *reinterpret_cast<const float4*>(bp1 + c*BWC + 8);
                const float bv0[12] = {p0.x,p0.y,p0.z,p0.w, p1.x,p1.y,p1.z,p1.w,
                                       p2.x,p2.y,p2.z,p2.w};
                const float bv1[12] = {q0.x,q0.y,q0.z,q0.w, q1.x,q1.y,q1.z,q1.w,
                                       q2.x,q2.y,q2.z,q2.w};
#pragma unroll
                for (int dx = 0; dx < 9; dx++) {
                    acc0[dx][0] += a0.x*bv0[dx+0];
                    acc0[dx][1] += a0.y*bv0[dx+1];
                    acc0[dx][2] += a0.z*bv0[dx+2];
                    acc0[dx][3] += a0.w*bv0[dx+3];
                    acc1[dx][0] += a1.x*bv1[dx+0];
                    acc1[dx][1] += a1.y*bv1[dx+1];
                    acc1[dx][2] += a1.z*bv1[dx+2];
                    acc1[dx][3] += a1.w*bv1[dx+3];
                }
            }
        }
        __syncthreads();
    }

    if (act) {
        float* op0 = out + ((size_t)(b*273 + dy*9)*HH + y0)*WW + x0t + xg*4;
        float* op1 = op0 + WW;
#pragma unroll
        for (int dx = 0; dx < 9; dx++) {
            float4 v0, v1;
            v0.x = lrelu(acc0[dx][0]); v0.y = lrelu(acc0[dx][1]);
            v0.z = lrelu(acc0[dx][2]); v0.w = lrelu(acc0[dx][3]);
            v1.x = lrelu(acc1[dx][0]); v1.y = lrelu(acc1[dx][1]);
            v1.z = lrelu(acc1[dx][2]); v1.w = lrelu(acc1[dx][3]);
            *reinterpret_cast<float4*>(op0 + (size_t)dx*HW) = v0;
            *reinterpret_cast<float4*>(op1 + (size_t)dx*HW) = v1;
        }
    }
}

// ===========================================================================
extern "C" void kernel_launch(void* const* d_in, const int* in_sizes, int n_in,
                              void* d_out, int out_size) {
    const float* x1   = (const float*)d_in[0];
    const float* x2   = (const float*)d_in[1];
    const float* r1   = (const float*)d_in[2];
    const float* flow = (const float*)d_in[3];
    float* out = (float*)d_out;

    cudaFuncSetAttribute(disp_kernel, cudaFuncAttributeMaxDynamicSharedMemorySize, DSP_SMEM);
    cudaFuncSetAttribute(corr_kernel, cudaFuncAttributeMaxDynamicSharedMemorySize, C2_SMEM);

    // 1) warp pass (serial prefix — corr depends on it, disp does not care)
    warp_kernel<<<dim3(1, HH, BB), 416>>>(x2, flow);

    // 2) fork: corr on the side stream, disp on the main (capture) stream —
    //    they are independent of each other and co-schedule on the chip.
    cudaEventRecord(g_si.e_fork, 0);
    cudaStreamWaitEvent(g_si.s, g_si.e_fork, 0);
    corr_kernel<<<dim3(WW/TXC, HH/2, BB), 256, C2_SMEM, g_si.s>>>(x1, out);
    disp_kernel<<<dim3(WW/TXD, HH, BB), 320, DSP_SMEM>>>(x1, r1, out);

    // 3) join: main stream waits for the side-stream work.
    cudaEventRecord(g_si.e_join, g_si.s);
    cudaStreamWaitEvent(0, g_si.e_join, 0);
}

// round 17
// speedup vs baseline: 1.0605x; 1.0605x over previous
#include <cuda_runtime.h>
#include <cuda_pipeline.h>

#define BB 4
#define CC 64
#define HH 128
#define WW 416
#define HW (HH*WW)
#define CHW (CC*HH*WW)

// Scratch for warped x2 (no cudaMalloc allowed)
__device__ float g_x2w[(size_t)BB*CHW];

__device__ __forceinline__ float lrelu(float v) { return v >= 0.f ? v : 0.1f*v; }

// Side stream + fork/join events, created once at process init (no device
// memory allocation; just stream/event handles).
struct StreamInit {
    cudaStream_t s;
    cudaEvent_t e_fork, e_join;
    StreamInit() {
        cudaStreamCreateWithFlags(&s, cudaStreamNonBlocking);
        cudaEventCreateWithFlags(&e_fork, cudaEventDisableTiming);
        cudaEventCreateWithFlags(&e_join, cudaEventDisableTiming);
    }
};
static StreamInit g_si;

// ===========================================================================
// Kernel 1: bilinear warp of x2 -> g_x2w. One pixel per thread, weights and
// indices register-resident, 64-c gather loop with deep unroll for MLP.
// (runs on the side stream, fully overlapped with disp_kernel)
// ===========================================================================
__global__ __launch_bounds__(416)
void warp_kernel(const float* __restrict__ x2, const float* __restrict__ flow) {
    const int x = threadIdx.x;            // 0..415
    const int y = blockIdx.y, b = blockIdx.z;

    const float fx = flow[((size_t)(b*2+0)*HH + y)*WW + x];
    const float fy = flow[((size_t)(b*2+1)*HH + y)*WW + x];
    const float gx = (float)x + fx;
    const float gy = (float)y + fy;
    const float x0f = floorf(gx), y0f = floorf(gy);
    const float wx = gx - x0f, wy = gy - y0f;
    const int x0 = (int)x0f, y0 = (int)y0f;
    const int x1i = x0 + 1,  y1i = y0 + 1;

    const float vx0 = (x0  >= 0 && x0  < WW) ? 1.f : 0.f;
    const float vx1 = (x1i >= 0 && x1i < WW) ? 1.f : 0.f;
    const float vy0 = (y0  >= 0 && y0  < HH) ? 1.f : 0.f;
    const float vy1 = (y1i >= 0 && y1i < HH) ? 1.f : 0.f;

    const int x0c = min(max(x0, 0), WW-1);
    const int x1c = min(max(x1i,0), WW-1);
    const int y0c = min(max(y0, 0), HH-1);
    const int y1c = min(max(y1i,0), HH-1);

    const float w00 = (1.f-wx)*(1.f-wy)*vx0*vy0;
    const float w01 = wx*(1.f-wy)*vx1*vy0;
    const float w10 = (1.f-wx)*wy*vx0*vy1;
    const float w11 = wx*wy*vx1*vy1;
    const int i00 = y0c*WW + x0c;
    const int i01 = y0c*WW + x1c;
    const int i10 = y1c*WW + x0c;
    const int i11 = y1c*WW + x1c;

    const float* xb = x2 + (size_t)b*CHW;
    float* ob = g_x2w + (size_t)b*CHW + (size_t)y*WW + x;
#pragma unroll 8
    for (int c = 0; c < CC; c++) {
        const float* p = xb + (size_t)c*HW;
        ob[(size_t)c*HW] = w00*__ldg(p+i00) + w01*__ldg(p+i01)
                         + w10*__ldg(p+i10) + w11*__ldg(p+i11);
    }
}

// ===========================================================================
// Kernel 2: 192-ch disparity cost volume (champion disp path, unchanged)
// ===========================================================================
#define TXD 104
#define RWD 296
#define CTD 16
#define NTD (CC/CTD)
#define DISP_BUF (CTD*TXD + CTD*RWD)    // 6400 floats per buffer
#define DSP_SMEM (2*DISP_BUF*4)         // 51200 B

__global__ __launch_bounds__(320, 2)
void disp_kernel(const float* __restrict__ x1, const float* __restrict__ r1,
                 float* __restrict__ out) {
    extern __shared__ float sm[];
    const int y = blockIdx.y, b = blockIdx.z;
    const int t = threadIdx.x;
    const int x0t = blockIdx.x * TXD;
    const int dg = t / 26;
    const int xg = t - dg*26;
    const bool act = (t < 312);

    const float* x1p = x1 + (size_t)b*CHW + (size_t)y*WW + x0t;
    const float* rp  = r1 + (size_t)b*CHW + (size_t)y*WW;

    float acc[16][4];
#pragma unroll
    for (int i = 0; i < 16; i++)
#pragma unroll
        for (int j = 0; j < 4; j++) acc[i][j] = 0.f;

    auto load_tile = [&](int bi, int kt) {
        float* da = sm + bi*DISP_BUF;
        float* dr = da + CTD*TXD;
        const int ct = kt * CTD;
#pragma unroll
        for (int i = t; i < CTD*26; i += 320) {
            int c = i / 26, x4 = (i - 26*c) * 4;
            __pipeline_memcpy_async(da + c*TXD + x4,
                                    x1p + (size_t)(ct+c)*HW + x4, 16);
        }
#pragma unroll
        for (int i = t; i < CTD*74; i += 320) {
            int c = i / 74, x4 = (i - 74*c) * 4;
            int gx = x0t - 96 + x4;
            float* dst = dr + c*RWD + x4;
            if ((unsigned)gx < WW)
                __pipeline_memcpy_async(dst, rp + (size_t)(ct+c)*HW + gx, 16);
            else
                *reinterpret_cast<float4*>(dst) = make_float4(0.f,0.f,0.f,0.f);
        }
    };

    load_tile(0, 0);
    __pipeline_commit();

    for (int k = 0; k < NTD; k++) {
        if (k + 1 < NTD) {
            load_tile((k+1) & 1, k+1);
            __pipeline_commit();
            __pipeline_wait_prior(1);
        } else {
            __pipeline_wait_prior(0);
        }
        __syncthreads();

        if (act) {
            const float* da = sm + (k&1)*DISP_BUF;
            const float* ap = da + xg*4;
            const float* bp = da + CTD*TXD + xg*4 + dg*16;
#pragma unroll 4
            for (int c = 0; c < CTD; c++) {
                const float4 a  = *reinterpret_cast<const float4*>(ap + c*TXD);
                const float4 q0 = *reinterpret_cast<const float4*>(bp + c*RWD);
                const float4 q1 = *reinterpret_cast<const float4*>(bp + c*RWD + 4);
                const float4 q2 = *reinterpret_cast<const float4*>(bp + c*RWD + 8);
                const float4 q3 = *reinterpret_cast<const float4*>(bp + c*RWD + 12);
                const float4 q4 = *reinterpret_cast<const float4*>(bp + c*RWD + 16);
                const float bv[20] = {q0.x,q0.y,q0.z,q0.w, q1.x,q1.y,q1.z,q1.w,
                                      q2.x,q2.y,q2.z,q2.w, q3.x,q3.y,q3.z,q3.w,
                                      q4.x,q4.y,q4.z,q4.w};
#pragma unroll
                for (int dj = 0; dj < 16; dj++) {
                    acc[dj][0] += a.x*bv[dj+0];
                    acc[dj][1] += a.y*bv[dj+1];
                    acc[dj][2] += a.z*bv[dj+2];
                    acc[dj][3] += a.w*bv[dj+3];
                }
            }
        }
        __syncthreads();
    }

    if (act) {
        float* op = out + ((size_t)(b*273 + 81 + dg*16)*HH + y)*WW + x0t + xg*4;
#pragma unroll
        for (int dj = 0; dj < 16; dj++) {
            float4 v;
            v.x = lrelu(acc[dj][0]);
            v.y = lrelu(acc[dj][1]);
            v.z = lrelu(acc[dj][2]);
            v.w = lrelu(acc[dj][3]);
            *reinterpret_cast<float4*>(op + (size_t)dj*HW) = v;
        }
    }
}

// ===========================================================================
// Kernel 3: 81-ch cost volume, 2 output rows per block (R14 champion)
// ===========================================================================
#define TXC 104
#define CTC 8
#define BWC 112
#define NTC (CC/CTC)
#define C2_AROWS 16                         // 2 ysub x 8 c
#define C2_BUF (C2_AROWS*TXC + 10*CTC*BWC)  // 10624 floats
#define C2_SMEM (2*C2_BUF*4)                // 84992 B

__global__ __launch_bounds__(256, 2)
void corr_kernel(const float* __restrict__ x1, float* __restrict__ out) {
    extern __shared__ float sm[];

    const int x0t = blockIdx.x * TXC;
    const int y0 = blockIdx.y * 2;
    const int b = blockIdx.z;
    const int t = threadIdx.x;
    const int dy = t / 26;
    const int xg = t - dy*26;
    const bool act = (t < 234);

    const float* x1b = x1 + (size_t)b*CHW + x0t;
    const float* wp  = g_x2w + (size_t)b*CHW;

    const int ca = t / 26, xa = (t - 26*ca) * 4;
    const int cb = t / 28, xb4 = (t - 28*cb) * 4;
    const int gx2 = x0t - 4 + xb4;
    const bool px = ((unsigned)gx2 < WW);

    float acc0[9][4], acc1[9][4];
#pragma unroll
    for (int i = 0; i < 9; i++)
#pragma unroll
        for (int j = 0; j < 4; j++) { acc0[i][j] = 0.f; acc1[i][j] = 0.f; }

    auto load_tile = [&](int bi, int kt) {
        float* da = sm + bi*C2_BUF;
        float* db = da + C2_AROWS*TXC;
        const int ct = kt * CTC;
        if (t < 208) {
            const float* s0 = x1b + (size_t)(ct+ca)*HW + (size_t)y0*WW + xa;
            __pipeline_memcpy_async(da + ca*TXC + xa, s0, 16);
            __pipeline_memcpy_async(da + (8+ca)*TXC + xa, s0 + WW, 16);
        }
        if (t < 224) {
            const float* srcb = wp + (size_t)(ct+cb)*HW + gx2;
            float* dstb = db + cb*BWC + xb4;
#pragma unroll
            for (int r = 0; r < 10; r++) {
                const int gy2 = y0 + r - 4;
                if (px && (unsigned)gy2 < HH)
                    __pipeline_memcpy_async(dstb + r*(CTC*BWC), srcb + gy2*WW, 16);
                else
                    *reinterpret_cast<float4*>(dstb + r*(CTC*BWC)) =
                        make_float4(0.f,0.f,0.f,0.f);
            }
        }
    };

    load_tile(0, 0);
    __pipeline_commit();

    for (int k = 0; k < NTC; k++) {
        if (k + 1 < NTC) {
            load_tile((k+1) & 1, k+1);
            __pipeline_commit();
            __pipeline_wait_prior(1);
        } else {
            __pipeline_wait_prior(0);
        }
        __syncthreads();

        if (act) {
            const float* da = sm + (k&1)*C2_BUF;
            const float* ap0 = da + xg*4;
            const float* ap1 = da + 8*TXC + xg*4;
            const float* bp0 = da + C2_AROWS*TXC + dy*(CTC*BWC) + xg*4;
            const float* bp1 = bp0 + (CTC*BWC);
#pragma unroll
            for (int c = 0; c < CTC; c++) {
                const float4 a0 = *reinterpret_cast<const float4*>(ap0 + c*TXC);
                const float4 a1 = *reinterpret_cast<const float4*>(ap1 + c*TXC);
                const float4 p0 = *reinterpret_cast<const float4*>(bp0 + c*BWC);
                const float4 p1 = *reinterpret_cast<const float4*>(bp0 + c*BWC + 4);
                const float4 p2 = *reinterpret_cast<const float4*>(bp0 + c*BWC + 8);
                const float4 q0 = *reinterpret_cast<const float4*>(bp1 + c*BWC);
                const float4 q1 = *reinterpret_cast<const float4*>(bp1 + c*BWC + 4);
                const float4 q2 = *reinterpret_cast<const float4*>(bp1 + c*BWC + 8);
                const float bv0[12] = {p0.x,p0.y,p0.z,p0.w, p1.x,p1.y,p1.z,p1.w,
                                       p2.x,p2.y,p2.z,p2.w};
                const float bv1[12] = {q0.x,q0.y,q0.z,q0.w, q1.x,q1.y,q1.z,q1.w,
                                       q2.x,q2.y,q2.z,q2.w};
#pragma unroll
                for (int dx = 0; dx < 9; dx++) {
                    acc0[dx][0] += a0.x*bv0[dx+0];
                    acc0[dx][1] += a0.y*bv0[dx+1];
                    acc0[dx][2] += a0.z*bv0[dx+2];
                    acc0[dx][3] += a0.w*bv0[dx+3];
                    acc1[dx][0] += a1.x*bv1[dx+0];
                    acc1[dx][1] += a1.y*bv1[dx+1];
                    acc1[dx][2] += a1.z*bv1[dx+2];
                    acc1[dx][3] += a1.w*bv1[dx+3];
                }
            }
        }
        __syncthreads();
    }

    if (act) {
        float* op0 = out + ((size_t)(b*273 + dy*9)*HH + y0)*WW + x0t + xg*4;
        float* op1 = op0 + WW;
#pragma unroll
        for (int dx = 0; dx < 9; dx++) {
            float4 v0, v1;
            v0.x = lrelu(acc0[dx][0]); v0.y = lrelu(acc0[dx][1]);
            v0.z = lrelu(acc0[dx][2]); v0.w = lrelu(acc0[dx][3]);
            v1.x = lrelu(acc1[dx][0]); v1.y = lrelu(acc1[dx][1]);
            v1.z = lrelu(acc1[dx][2]); v1.w = lrelu(acc1[dx][3]);
            *reinterpret_cast<float4*>(op0 + (size_t)dx*HW) = v0;
            *reinterpret_cast<float4*>(op1 + (size_t)dx*HW) = v1;
        }
    }
}

// ===========================================================================
extern "C" void kernel_launch(void* const* d_in, const int* in_sizes, int n_in,
                              void* d_out, int out_size) {
    const float* x1   = (const float*)d_in[0];
    const float* x2   = (const float*)d_in[1];
    const float* r1   = (const float*)d_in[2];
    const float* flow = (const float*)d_in[3];
    float* out = (float*)d_out;

    cudaFuncSetAttribute(disp_kernel, cudaFuncAttributeMaxDynamicSharedMemorySize, DSP_SMEM);
    cudaFuncSetAttribute(corr_kernel, cudaFuncAttributeMaxDynamicSharedMemorySize, C2_SMEM);

    // Fork at t=0: side stream runs warp -> corr (dependency kept by stream
    // order); main stream runs disp concurrently the whole time.
    cudaEventRecord(g_si.e_fork, 0);
    cudaStreamWaitEvent(g_si.s, g_si.e_fork, 0);

    warp_kernel<<<dim3(1, HH, BB), 416, 0, g_si.s>>>(x2, flow);
    corr_kernel<<<dim3(WW/TXC, HH/2, BB), 256, C2_SMEM, g_si.s>>>(x1, out);

    disp_kernel<<<dim3(WW/TXD, HH, BB), 320, DSP_SMEM>>>(x1, r1, out);

    // Join: main stream waits for the side-stream chain.
    cudaEventRecord(g_si.e_join, g_si.s);
    cudaStreamWaitEvent(0, g_si.e_join, 0);
}